// round 11
// baseline (speedup 1.0000x reference)
#include <cuda_runtime.h>
#include <cuda_bf16.h>
#include <cuda_fp16.h>
#include <math.h>
#include <stdint.h>

// ---------------- problem constants ----------------
#define BWIN   512
#define NTOK   144
#define CDIM   512
#define HEADS  16
#define DHEAD  32
#define NW     64
#define MROWS  (BWIN * NTOK)        // 73728
#define QKVC   (3 * CDIM)           // 1536
#define NPOS   (23 * 23)
#define CPBH   512

// ---------------- scratch ----------------
__device__ float g_qkv [(size_t)MROWS * QKVC];
__device__ float g_att [(size_t)MROWS * CDIM];
__device__ float g_tbl [NPOS * HEADS];
__device__ float g_bias[(size_t)HEADS * NTOK * NTOK];

__device__ __forceinline__ uint32_t s2u(const void* p) {
    return (uint32_t)__cvta_generic_to_shared(p);
}
__device__ __forceinline__ uint2 f4_to_h4(float4 v) {
    __half2 h0 = __float22half2_rn(make_float2(v.x, v.y));
    __half2 h1 = __float22half2_rn(make_float2(v.z, v.w));
    uint2 u;
    u.x = *(uint32_t*)&h0;
    u.y = *(uint32_t*)&h1;
    return u;
}
__device__ __forceinline__ void split_pack(float x, float y, uint32_t& hi, uint32_t& lo) {
    __half hx = __float2half_rn(x), hy = __float2half_rn(y);
    __half2 h = __halves2half2(hx, hy);
    hi = *(uint32_t*)&h;
    __half2 l = __floats2half2_rn(x - __half2float(hx), y - __half2float(hy));
    lo = *(uint32_t*)&l;
}
__device__ __forceinline__ uint32_t pack_h2(float x, float y) {
    __half2 h = __floats2half2_rn(x, y);
    return *(uint32_t*)&h;
}

#define MMA_F16(d, a0,a1,a2,a3, b0,b1)                                         \
    asm volatile("mma.sync.aligned.m16n8k16.row.col.f32.f16.f16.f32 "          \
                 "{%0,%1,%2,%3},{%4,%5,%6,%7},{%8,%9},{%0,%1,%2,%3};"          \
                 : "+f"(d[0]), "+f"(d[1]), "+f"(d[2]), "+f"(d[3])              \
                 : "r"(a0), "r"(a1), "r"(a2), "r"(a3), "r"(b0), "r"(b1))

#define LDSM_X4(r0,r1,r2,r3, addr)                                             \
    asm volatile("ldmatrix.sync.aligned.m8n8.x4.shared.b16 {%0,%1,%2,%3}, [%4];" \
                 : "=r"(r0), "=r"(r1), "=r"(r2), "=r"(r3) : "r"(addr))

// =========================================================================
// FP16 tensor-core GEMM (NT) — unchanged from R10 (at legacy-mma ceiling)
// =========================================================================
#define GBK    32
#define GLDH   40
#define ABUFH  (128 * GLDH)
#define BBUFH  (256 * GLDH)
#define GT_SMEM_BYTES ((2 * ABUFH + 2 * BBUFH) * 2)   // 61440

template <bool HAS_BIAS>
__global__ __launch_bounds__(512, 1)
void gemm_f16_nt(const float* __restrict__ A,
                 const float* __restrict__ B,
                 const float* __restrict__ bias,
                 float* __restrict__ C,
                 int M, int N, int K)
{
    extern __shared__ __align__(16) __half gsm[];
    __half* As = gsm;
    __half* Bs = gsm + 2 * ABUFH;

    const int tid  = threadIdx.x;
    const int lane = tid & 31;
    const int warp = tid >> 5;
    const int warpM = (warp & 3) * 32;
    const int warpN = (warp >> 2) * 64;
    const int rowBase = blockIdx.y * 128;
    const int colBase = blockIdx.x * 256;

    const int r  = tid >> 3;
    const int kq = tid & 7;
    const float* Ag = A + (size_t)(rowBase + r) * K + kq * 4;
    const float* Bg = B + (size_t)(colBase + r) * K + kq * 4;

    float4 ra[2], rb[4];

    float acc[2][8][4];
#pragma unroll
    for (int mi = 0; mi < 2; mi++)
#pragma unroll
        for (int ni = 0; ni < 8; ni++)
#pragma unroll
            for (int c = 0; c < 4; c++) acc[mi][ni][c] = 0.f;

    const uint32_t aOff = (uint32_t)((warpM + (lane & 7) + ((lane >> 3) & 1) * 8) * (GLDH * 2))
                        + (uint32_t)(lane >> 4) * 16;
    const uint32_t bOff = (uint32_t)((warpN + (lane & 7) + ((lane & 16) ? 8 : 0)) * (GLDH * 2))
                        + (uint32_t)((lane >> 3) & 1) * 16;
    const uint32_t asBase = s2u(As);
    const uint32_t bsBase = s2u(Bs);

#define G_LOAD(it)  {                                                \
        const float* ap = Ag + (it) * GBK;                           \
        const float* bp = Bg + (it) * GBK;                           \
        ra[0] = *(const float4*)(ap);                                \
        ra[1] = *(const float4*)(ap + (size_t)64 * K);               \
        rb[0] = *(const float4*)(bp);                                \
        rb[1] = *(const float4*)(bp + (size_t)64 * K);               \
        rb[2] = *(const float4*)(bp + (size_t)128 * K);              \
        rb[3] = *(const float4*)(bp + (size_t)192 * K);              \
    }
#define G_STS(buf)  {                                                           \
        _Pragma("unroll")                                                       \
        for (int i = 0; i < 2; i++)                                             \
            *(uint2*)&As[(buf) * ABUFH + (r + 64 * i) * GLDH + kq * 4] = f4_to_h4(ra[i]); \
        _Pragma("unroll")                                                       \
        for (int i = 0; i < 4; i++)                                             \
            *(uint2*)&Bs[(buf) * BBUFH + (r + 64 * i) * GLDH + kq * 4] = f4_to_h4(rb[i]); \
    }

    G_LOAD(0); G_STS(0); __syncthreads();

    const int NIT = K / GBK;
    for (int it = 0; it < NIT; ++it) {
        const int buf = it & 1;
        if (it + 1 < NIT) G_LOAD(it + 1);

        const uint32_t aB = asBase + (uint32_t)buf * (ABUFH * 2);
        const uint32_t bB = bsBase + (uint32_t)buf * (BBUFH * 2);

#pragma unroll
        for (int kk = 0; kk < 2; kk++) {
            uint32_t a[2][4], bf[8][2];
#pragma unroll
            for (int mi = 0; mi < 2; mi++) {
                uint32_t addr = aB + aOff + (uint32_t)(mi * 16 * GLDH * 2) + (uint32_t)(kk * 32);
                LDSM_X4(a[mi][0], a[mi][1], a[mi][2], a[mi][3], addr);
            }
#pragma unroll
            for (int p = 0; p < 4; p++) {
                uint32_t addr = bB + bOff + (uint32_t)(p * 16 * GLDH * 2) + (uint32_t)(kk * 32);
                uint32_t r0, r1, r2, r3;
                LDSM_X4(r0, r1, r2, r3, addr);
                bf[2 * p][0] = r0; bf[2 * p][1] = r1;
                bf[2 * p + 1][0] = r2; bf[2 * p + 1][1] = r3;
            }
#pragma unroll
            for (int mi = 0; mi < 2; mi++)
#pragma unroll
                for (int ni = 0; ni < 8; ni++)
                    MMA_F16(acc[mi][ni], a[mi][0], a[mi][1], a[mi][2], a[mi][3],
                            bf[ni][0], bf[ni][1]);
        }
        if (it + 1 < NIT) G_STS(buf ^ 1);
        __syncthreads();
    }

    const int g  = lane >> 2;
    const int cq = (lane & 3) * 2;
#pragma unroll
    for (int mi = 0; mi < 2; mi++) {
        const int row0 = rowBase + warpM + mi * 16 + g;
#pragma unroll
        for (int ni = 0; ni < 8; ni++) {
            const int col = colBase + warpN + ni * 8 + cq;
            float b0 = 0.f, b1 = 0.f;
            if (HAS_BIAS) { b0 = bias[col]; b1 = bias[col + 1]; }
            *(float2*)&C[(size_t)row0 * N + col] =
                make_float2(acc[mi][ni][0] + b0, acc[mi][ni][1] + b1);
            *(float2*)&C[(size_t)(row0 + 8) * N + col] =
                make_float2(acc[mi][ni][2] + b0, acc[mi][ni][3] + b1);
        }
    }
#undef G_LOAD
#undef G_STS
}

// =========================================================================
// CPB MLP table + bias gather (tiny, unchanged)
// =========================================================================
__global__ __launch_bounds__(512)
void cpb_tbl_kernel(const float* __restrict__ rel_table,
                    const float* __restrict__ w1,
                    const float* __restrict__ b1,
                    const float* __restrict__ w2,
                    float* __restrict__ tbl)
{
    __shared__ float hid[CPBH];
    int p = blockIdx.x;
    float t0 = rel_table[2 * p], t1 = rel_table[2 * p + 1];
    int j = threadIdx.x;
    hid[j] = fmaxf(t0 * w1[2 * j] + t1 * w1[2 * j + 1] + b1[j], 0.f);
    __syncthreads();

    int warp = j >> 5, lane = j & 31;
    const float* w2h = w2 + warp * CPBH;
    float s = 0.f;
#pragma unroll
    for (int q = lane; q < CPBH; q += 32) s += hid[q] * w2h[q];
#pragma unroll
    for (int o = 16; o > 0; o >>= 1) s += __shfl_xor_sync(0xffffffffu, s, o);
    if (lane == 0) tbl[p * HEADS + warp] = s;
}

__global__ void bias_gather_kernel(const float* __restrict__ tbl,
                                   const int* __restrict__ rel_index,
                                   float* __restrict__ bias)
{
    int t = blockIdx.x * blockDim.x + threadIdx.x;
    const int TOT = HEADS * NTOK * NTOK;
    if (t >= TOT) return;
    int h  = t / (NTOK * NTOK);
    int ij = t % (NTOK * NTOK);
    float x = tbl[rel_index[ij] * HEADS + h];
    bias[(size_t)h * NTOK * NTOK + ij] = 16.f / (1.f + __expf(-x));
}

// =========================================================================
// Window attention v5: same math as v4 (split-fp16 QK, plain-fp16 PV) but
// CTA = 6 warps / 192 threads owning 3 query tiles; grid (HEADS, BWIN, 3);
// 3 CTAs co-resident per SM overlap each other's latency chains.
// =========================================================================
#define KSTR_H 40
#define VSTR_H 152
#define PVSTR  18
#define TPC    3                                     // tiles per CTA

#define AK_KHI 0
#define AK_KLO (AK_KHI + NTOK * KSTR_H * 2)          // 11520
#define AK_VHI (AK_KLO + NTOK * KSTR_H * 2)          // 23040
#define AK_PVB (AK_VHI + DHEAD * VSTR_H * 2)         // 32768
#define AK_SUM (AK_PVB + TPC * 32 * PVSTR * 4)       // 39680
#define ATTN_SMEM_BYTES (AK_SUM + TPC * 2 * 32 * 4)  // 40448

__global__ __launch_bounds__(192, 3)
void attn_tc5_kernel(const float* __restrict__ qkv,
                     const float* __restrict__ bias,
                     const float* __restrict__ mask,
                     const float* __restrict__ logit_scale,
                     float* __restrict__ out)
{
    extern __shared__ __align__(16) char dsm[];

    const int h = blockIdx.x;
    const int b = blockIdx.y;
    const int w = b & (NW - 1);

    const int tid  = threadIdx.x;
    const int lane = tid & 31;
    const int warp = tid >> 5;               // 0..5
    const int pairL = warp % TPC;            // local tile 0..2
    const int half  = warp / TPC;            // 0: cols 0..63, 1: 64..143
    const int ng    = half ? 5 : 4;
    const int hbase = half ? 64 : 0;
    const int g  = lane >> 2;
    const int t  = lane & 3;
    const int R0 = (blockIdx.z * TPC + pairL) * 16;

    const float scale = __expf(fminf(logit_scale[h], 4.60517018598809f));
    const float* base = qkv + (size_t)b * NTOK * QKVC + h * DHEAD;

    __half* knHi = (__half*)(dsm + AK_KHI);
    __half* knLo = (__half*)(dsm + AK_KLO);
    __half* vtHi = (__half*)(dsm + AK_VHI);
    float*  pvb  = (float*)(dsm + AK_PVB);
    float*  sumb = (float*)(dsm + AK_SUM);
    const uint32_t knHiB = s2u(knHi);
    const uint32_t knLoB = s2u(knLo);
    const uint32_t vtHiB = s2u(vtHi);

    // ---------- load K (normalized, hi/lo fp16) and V^T (hi fp16): 24 rows/warp
#pragma unroll 4
    for (int i = 0; i < NTOK / 6; i++) {
        int j = warp * (NTOK / 6) + i;
        float kv = base[(size_t)j * QKVC + CDIM + lane];
        float s = kv * kv;
#pragma unroll
        for (int o = 16; o > 0; o >>= 1) s += __shfl_xor_sync(0xffffffffu, s, o);
        kv *= rsqrtf(s);
        __half khi = __float2half_rn(kv);
        knHi[j * KSTR_H + lane] = khi;
        knLo[j * KSTR_H + lane] = __float2half_rn(kv - __half2float(khi));

        float vv = base[(size_t)j * QKVC + 2 * CDIM + lane];
        vtHi[lane * VSTR_H + j] = __float2half_rn(vv);
    }

    // ---------- Q fragments (normalized + scaled, split fp16) ----------
    uint32_t qah[2][4], qal[2][4];
    {
        const float* q0 = base + (size_t)(R0 + g) * QKVC;
        const float* q1 = base + (size_t)(R0 + g + 8) * QKVC;
        float e0[2][4], e1[2][4];
#pragma unroll
        for (int kc = 0; kc < 2; kc++) {
            e0[kc][0] = q0[16 * kc + 2 * t];     e0[kc][1] = q0[16 * kc + 2 * t + 1];
            e0[kc][2] = q0[16 * kc + 8 + 2 * t]; e0[kc][3] = q0[16 * kc + 9 + 2 * t];
            e1[kc][0] = q1[16 * kc + 2 * t];     e1[kc][1] = q1[16 * kc + 2 * t + 1];
            e1[kc][2] = q1[16 * kc + 8 + 2 * t]; e1[kc][3] = q1[16 * kc + 9 + 2 * t];
        }
        float s0 = 0.f, s1 = 0.f;
#pragma unroll
        for (int kc = 0; kc < 2; kc++)
#pragma unroll
            for (int i = 0; i < 4; i++) {
                s0 += e0[kc][i] * e0[kc][i];
                s1 += e1[kc][i] * e1[kc][i];
            }
        s0 += __shfl_xor_sync(0xffffffffu, s0, 1);
        s0 += __shfl_xor_sync(0xffffffffu, s0, 2);
        s1 += __shfl_xor_sync(0xffffffffu, s1, 1);
        s1 += __shfl_xor_sync(0xffffffffu, s1, 2);
        float r0 = rsqrtf(s0) * scale, r1 = rsqrtf(s1) * scale;
#pragma unroll
        for (int kc = 0; kc < 2; kc++) {
            split_pack(e0[kc][0] * r0, e0[kc][1] * r0, qah[kc][0], qal[kc][0]);
            split_pack(e1[kc][0] * r1, e1[kc][1] * r1, qah[kc][1], qal[kc][1]);
            split_pack(e0[kc][2] * r0, e0[kc][3] * r0, qah[kc][2], qal[kc][2]);
            split_pack(e1[kc][2] * r1, e1[kc][3] * r1, qah[kc][3], qal[kc][3]);
        }
    }
    __syncthreads();

    // ---------- QK^T (split fp16, 3 terms): acc[2*ng][4] ----------
    float acc[10][4];
#pragma unroll
    for (int nt = 0; nt < 10; nt++)
#pragma unroll
        for (int c = 0; c < 4; c++) acc[nt][c] = 0.f;

    const uint32_t ldsmRow = (uint32_t)((lane & 7) + ((lane & 16) ? 8 : 0));
    const uint32_t ldsmCol = (uint32_t)((lane >> 3) & 1) * 16;

#pragma unroll
    for (int kc = 0; kc < 2; kc++) {
#pragma unroll
        for (int gI = 0; gI < 5; gI++) {
            if (gI < ng) {
                uint32_t off = (uint32_t)(hbase + gI * 16 + ldsmRow) * (KSTR_H * 2)
                             + ldsmCol + (uint32_t)kc * 32;
                uint32_t bh0, bh1, bh2, bh3, bl0, bl1, bl2, bl3;
                LDSM_X4(bh0, bh1, bh2, bh3, knHiB + off);
                LDSM_X4(bl0, bl1, bl2, bl3, knLoB + off);
                MMA_F16(acc[2 * gI],     qah[kc][0], qah[kc][1], qah[kc][2], qah[kc][3], bh0, bh1);
                MMA_F16(acc[2 * gI],     qah[kc][0], qah[kc][1], qah[kc][2], qah[kc][3], bl0, bl1);
                MMA_F16(acc[2 * gI],     qal[kc][0], qal[kc][1], qal[kc][2], qal[kc][3], bh0, bh1);
                MMA_F16(acc[2 * gI + 1], qah[kc][0], qah[kc][1], qah[kc][2], qah[kc][3], bh2, bh3);
                MMA_F16(acc[2 * gI + 1], qah[kc][0], qah[kc][1], qah[kc][2], qah[kc][3], bl2, bl3);
                MMA_F16(acc[2 * gI + 1], qal[kc][0], qal[kc][1], qal[kc][2], qal[kc][3], bh2, bh3);
            }
        }
    }

    // ---------- bias + mask, local max, exp, local sums ----------
    float mx0 = -1e30f, mx1 = -1e30f, sm0 = 0.f, sm1 = 0.f;
    {
        const float* biasR0 = bias + (size_t)h * NTOK * NTOK + (size_t)(R0 + g) * NTOK + hbase + 2 * t;
        const float* biasR1 = biasR0 + 8 * NTOK;
        const float* maskR0 = mask + (size_t)w * NTOK * NTOK + (size_t)(R0 + g) * NTOK + hbase + 2 * t;
        const float* maskR1 = maskR0 + 8 * NTOK;
#pragma unroll
        for (int nt = 0; nt < 10; nt++) {
            if (nt < 2 * ng) {
                float2 bb0 = *(const float2*)(biasR0 + 8 * nt);
                float2 mm0 = *(const float2*)(maskR0 + 8 * nt);
                float2 bb1 = *(const float2*)(biasR1 + 8 * nt);
                float2 mm1 = *(const float2*)(maskR1 + 8 * nt);
                acc[nt][0] += bb0.x + mm0.x;
                acc[nt][1] += bb0.y + mm0.y;
                acc[nt][2] += bb1.x + mm1.x;
                acc[nt][3] += bb1.y + mm1.y;
                mx0 = fmaxf(mx0, fmaxf(acc[nt][0], acc[nt][1]));
                mx1 = fmaxf(mx1, fmaxf(acc[nt][2], acc[nt][3]));
            }
        }
        mx0 = fmaxf(mx0, __shfl_xor_sync(0xffffffffu, mx0, 1));
        mx0 = fmaxf(mx0, __shfl_xor_sync(0xffffffffu, mx0, 2));
        mx1 = fmaxf(mx1, __shfl_xor_sync(0xffffffffu, mx1, 1));
        mx1 = fmaxf(mx1, __shfl_xor_sync(0xffffffffu, mx1, 2));
#pragma unroll
        for (int nt = 0; nt < 10; nt++) {
            if (nt < 2 * ng) {
                acc[nt][0] = __expf(acc[nt][0] - mx0);
                acc[nt][1] = __expf(acc[nt][1] - mx0);
                acc[nt][2] = __expf(acc[nt][2] - mx1);
                acc[nt][3] = __expf(acc[nt][3] - mx1);
                sm0 += acc[nt][0] + acc[nt][1];
                sm1 += acc[nt][2] + acc[nt][3];
            }
        }
        sm0 += __shfl_xor_sync(0xffffffffu, sm0, 1);
        sm0 += __shfl_xor_sync(0xffffffffu, sm0, 2);
        sm1 += __shfl_xor_sync(0xffffffffu, sm1, 1);
        sm1 += __shfl_xor_sync(0xffffffffu, sm1, 2);
        if (t == 0) {
            float* sb = sumb + (pairL * 2 + half) * 32;
            sb[g]          = sm0;
            sb[g + 8]      = sm1;
            sb[16 + g]     = mx0;
            sb[16 + g + 8] = mx1;
        }
    }

    // ---------- PV (plain fp16: P_hi x V_hi) ----------
    float pv[4][4];
#pragma unroll
    for (int nt = 0; nt < 4; nt++)
#pragma unroll
        for (int c = 0; c < 4; c++) pv[nt][c] = 0.f;

#pragma unroll
    for (int kc2 = 0; kc2 < 5; kc2++) {
        if (kc2 < ng) {
            uint32_t ph[4];
            ph[0] = pack_h2(acc[2 * kc2][0],     acc[2 * kc2][1]);
            ph[1] = pack_h2(acc[2 * kc2][2],     acc[2 * kc2][3]);
            ph[2] = pack_h2(acc[2 * kc2 + 1][0], acc[2 * kc2 + 1][1]);
            ph[3] = pack_h2(acc[2 * kc2 + 1][2], acc[2 * kc2 + 1][3]);
            const uint32_t gk = (uint32_t)((hbase >> 4) + kc2);
#pragma unroll
            for (int p = 0; p < 2; p++) {
                uint32_t off = (uint32_t)(p * 16 + ldsmRow) * (VSTR_H * 2)
                             + ldsmCol + gk * 32;
                uint32_t bh0, bh1, bh2, bh3;
                LDSM_X4(bh0, bh1, bh2, bh3, vtHiB + off);
                MMA_F16(pv[2 * p],     ph[0], ph[1], ph[2], ph[3], bh0, bh1);
                MMA_F16(pv[2 * p + 1], ph[0], ph[1], ph[2], ph[3], bh2, bh3);
            }
        }
    }

    // ---------- pairwise combine (max-corrected) + epilogue ----------
    if (half == 1) {
        float* pb = pvb + (pairL * 32 + lane) * PVSTR;
#pragma unroll
        for (int nt = 0; nt < 4; nt++) {
            *(float2*)(pb + nt * 4)     = make_float2(pv[nt][0], pv[nt][1]);
            *(float2*)(pb + nt * 4 + 2) = make_float2(pv[nt][2], pv[nt][3]);
        }
    }
    __syncthreads();
    if (half == 0) {
        const float* sbO = sumb + (pairL * 2 + 1) * 32;
        const float smO0 = sbO[g],      mxO0 = sbO[16 + g];
        const float smO1 = sbO[g + 8],  mxO1 = sbO[16 + g + 8];
        const float M0 = fmaxf(mx0, mxO0);
        const float M1 = fmaxf(mx1, mxO1);
        const float fl0 = __expf(mx0 - M0), fo0 = __expf(mxO0 - M0);
        const float fl1 = __expf(mx1 - M1), fo1 = __expf(mxO1 - M1);
        const float inv0 = 1.f / (sm0 * fl0 + smO0 * fo0);
        const float inv1 = 1.f / (sm1 * fl1 + smO1 * fo1);
        const float* pb = pvb + (pairL * 32 + lane) * PVSTR;
        float* o0 = out + ((size_t)b * NTOK + R0 + g) * CDIM + h * DHEAD + 2 * t;
        float* o1 = o0 + (size_t)8 * CDIM;
#pragma unroll
        for (int nt = 0; nt < 4; nt++) {
            float2 q0 = *(const float2*)(pb + nt * 4);
            float2 q1 = *(const float2*)(pb + nt * 4 + 2);
            *(float2*)(o0 + 8 * nt) = make_float2((pv[nt][0] * fl0 + q0.x * fo0) * inv0,
                                                  (pv[nt][1] * fl0 + q0.y * fo0) * inv0);
            *(float2*)(o1 + 8 * nt) = make_float2((pv[nt][2] * fl1 + q1.x * fo1) * inv1,
                                                  (pv[nt][3] * fl1 + q1.y * fo1) * inv1);
        }
    }
}

// =========================================================================
// launch
// =========================================================================
extern "C" void kernel_launch(void* const* d_in, const int* in_sizes, int n_in,
                              void* d_out, int out_size)
{
    const float* x           = (const float*)d_in[0];
    const float* mask        = (const float*)d_in[1];
    const float* qkv_w       = (const float*)d_in[2];
    const float* logit_scale = (const float*)d_in[3];
    const float* cpb_w1      = (const float*)d_in[4];
    const float* cpb_b1      = (const float*)d_in[5];
    const float* cpb_w2      = (const float*)d_in[6];
    const float* proj_w      = (const float*)d_in[7];
    const float* proj_b      = (const float*)d_in[8];
    const float* rel_table   = (const float*)d_in[9];
    const int*   rel_index   = (const int*)d_in[10];
    float* out = (float*)d_out;

    float *qkv, *att, *tbl, *bias;
    cudaGetSymbolAddress((void**)&qkv,  g_qkv);
    cudaGetSymbolAddress((void**)&att,  g_att);
    cudaGetSymbolAddress((void**)&tbl,  g_tbl);
    cudaGetSymbolAddress((void**)&bias, g_bias);

    cudaFuncSetAttribute(gemm_f16_nt<false>,
                         cudaFuncAttributeMaxDynamicSharedMemorySize, GT_SMEM_BYTES);
    cudaFuncSetAttribute(gemm_f16_nt<true>,
                         cudaFuncAttributeMaxDynamicSharedMemorySize, GT_SMEM_BYTES);
    cudaFuncSetAttribute(attn_tc5_kernel,
                         cudaFuncAttributeMaxDynamicSharedMemorySize, ATTN_SMEM_BYTES);

    // 1) QKV projection (fp16 m16n8k16)
    {
        dim3 grid(QKVC / 256, MROWS / 128);
        gemm_f16_nt<false><<<grid, 512, GT_SMEM_BYTES>>>(x, qkv_w, nullptr, qkv,
                                                         MROWS, QKVC, CDIM);
    }

    // 2) relative position bias table + gather
    cpb_tbl_kernel<<<NPOS, CPBH>>>(rel_table, cpb_w1, cpb_b1, cpb_w2, tbl);
    {
        int tot = HEADS * NTOK * NTOK;
        bias_gather_kernel<<<(tot + 255) / 256, 256>>>(tbl, rel_index, bias);
    }

    // 3) attention v5: 6-warp CTAs, 3 tiles each, 3 CTAs/SM
    {
        dim3 grid(HEADS, BWIN, 3);
        attn_tc5_kernel<<<grid, 192, ATTN_SMEM_BYTES>>>(qkv, bias, mask, logit_scale, att);
    }

    // 4) output projection (fp16 m16n8k16)
    {
        dim3 grid(CDIM / 256, MROWS / 128);
        gemm_f16_nt<true><<<grid, 512, GT_SMEM_BYTES>>>(att, proj_w, proj_b, out,
                                                        MROWS, CDIM, CDIM);
    }
}

// round 12
// speedup vs baseline: 1.1337x; 1.1337x over previous
#include <cuda_runtime.h>
#include <cuda_bf16.h>
#include <cuda_fp16.h>
#include <math.h>
#include <stdint.h>

// ---------------- problem constants ----------------
#define BWIN   512
#define NTOK   144
#define CDIM   512
#define HEADS  16
#define DHEAD  32
#define NW     64
#define MROWS  (BWIN * NTOK)        // 73728
#define QKVC   (3 * CDIM)           // 1536
#define NPOS   (23 * 23)
#define CPBH   512

// ---------------- scratch ----------------
__device__ float g_qkv [(size_t)MROWS * QKVC];
__device__ float g_att [(size_t)MROWS * CDIM];
__device__ float g_tbl [NPOS * HEADS];
__device__ float g_bias[(size_t)HEADS * NTOK * NTOK];

__device__ __forceinline__ uint32_t s2u(const void* p) {
    return (uint32_t)__cvta_generic_to_shared(p);
}
__device__ __forceinline__ uint2 f4_to_h4(float4 v) {
    __half2 h0 = __float22half2_rn(make_float2(v.x, v.y));
    __half2 h1 = __float22half2_rn(make_float2(v.z, v.w));
    uint2 u;
    u.x = *(uint32_t*)&h0;
    u.y = *(uint32_t*)&h1;
    return u;
}
__device__ __forceinline__ void split_pack(float x, float y, uint32_t& hi, uint32_t& lo) {
    __half hx = __float2half_rn(x), hy = __float2half_rn(y);
    __half2 h = __halves2half2(hx, hy);
    hi = *(uint32_t*)&h;
    __half2 l = __floats2half2_rn(x - __half2float(hx), y - __half2float(hy));
    lo = *(uint32_t*)&l;
}
__device__ __forceinline__ uint32_t pack_h2(float x, float y) {
    __half2 h = __floats2half2_rn(x, y);
    return *(uint32_t*)&h;
}

#define MMA_F16(d, a0,a1,a2,a3, b0,b1)                                         \
    asm volatile("mma.sync.aligned.m16n8k16.row.col.f32.f16.f16.f32 "          \
                 "{%0,%1,%2,%3},{%4,%5,%6,%7},{%8,%9},{%0,%1,%2,%3};"          \
                 : "+f"(d[0]), "+f"(d[1]), "+f"(d[2]), "+f"(d[3])              \
                 : "r"(a0), "r"(a1), "r"(a2), "r"(a3), "r"(b0), "r"(b1))

#define LDSM_X4(r0,r1,r2,r3, addr)                                             \
    asm volatile("ldmatrix.sync.aligned.m8n8.x4.shared.b16 {%0,%1,%2,%3}, [%4];" \
                 : "=r"(r0), "=r"(r1), "=r"(r2), "=r"(r3) : "r"(addr))

// =========================================================================
// FP16 tensor-core GEMM (NT) — unchanged from R10 (at legacy-mma ceiling)
// =========================================================================
#define GBK    32
#define GLDH   40
#define ABUFH  (128 * GLDH)
#define BBUFH  (256 * GLDH)
#define GT_SMEM_BYTES ((2 * ABUFH + 2 * BBUFH) * 2)   // 61440

template <bool HAS_BIAS>
__global__ __launch_bounds__(512, 1)
void gemm_f16_nt(const float* __restrict__ A,
                 const float* __restrict__ B,
                 const float* __restrict__ bias,
                 float* __restrict__ C,
                 int M, int N, int K)
{
    extern __shared__ __align__(16) __half gsm[];
    __half* As = gsm;
    __half* Bs = gsm + 2 * ABUFH;

    const int tid  = threadIdx.x;
    const int lane = tid & 31;
    const int warp = tid >> 5;
    const int warpM = (warp & 3) * 32;
    const int warpN = (warp >> 2) * 64;
    const int rowBase = blockIdx.y * 128;
    const int colBase = blockIdx.x * 256;

    const int r  = tid >> 3;
    const int kq = tid & 7;
    const float* Ag = A + (size_t)(rowBase + r) * K + kq * 4;
    const float* Bg = B + (size_t)(colBase + r) * K + kq * 4;

    float4 ra[2], rb[4];

    float acc[2][8][4];
#pragma unroll
    for (int mi = 0; mi < 2; mi++)
#pragma unroll
        for (int ni = 0; ni < 8; ni++)
#pragma unroll
            for (int c = 0; c < 4; c++) acc[mi][ni][c] = 0.f;

    const uint32_t aOff = (uint32_t)((warpM + (lane & 7) + ((lane >> 3) & 1) * 8) * (GLDH * 2))
                        + (uint32_t)(lane >> 4) * 16;
    const uint32_t bOff = (uint32_t)((warpN + (lane & 7) + ((lane & 16) ? 8 : 0)) * (GLDH * 2))
                        + (uint32_t)((lane >> 3) & 1) * 16;
    const uint32_t asBase = s2u(As);
    const uint32_t bsBase = s2u(Bs);

#define G_LOAD(it)  {                                                \
        const float* ap = Ag + (it) * GBK;                           \
        const float* bp = Bg + (it) * GBK;                           \
        ra[0] = *(const float4*)(ap);                                \
        ra[1] = *(const float4*)(ap + (size_t)64 * K);               \
        rb[0] = *(const float4*)(bp);                                \
        rb[1] = *(const float4*)(bp + (size_t)64 * K);               \
        rb[2] = *(const float4*)(bp + (size_t)128 * K);              \
        rb[3] = *(const float4*)(bp + (size_t)192 * K);              \
    }
#define G_STS(buf)  {                                                           \
        _Pragma("unroll")                                                       \
        for (int i = 0; i < 2; i++)                                             \
            *(uint2*)&As[(buf) * ABUFH + (r + 64 * i) * GLDH + kq * 4] = f4_to_h4(ra[i]); \
        _Pragma("unroll")                                                       \
        for (int i = 0; i < 4; i++)                                             \
            *(uint2*)&Bs[(buf) * BBUFH + (r + 64 * i) * GLDH + kq * 4] = f4_to_h4(rb[i]); \
    }

    G_LOAD(0); G_STS(0); __syncthreads();

    const int NIT = K / GBK;
    for (int it = 0; it < NIT; ++it) {
        const int buf = it & 1;
        if (it + 1 < NIT) G_LOAD(it + 1);

        const uint32_t aB = asBase + (uint32_t)buf * (ABUFH * 2);
        const uint32_t bB = bsBase + (uint32_t)buf * (BBUFH * 2);

#pragma unroll
        for (int kk = 0; kk < 2; kk++) {
            uint32_t a[2][4], bf[8][2];
#pragma unroll
            for (int mi = 0; mi < 2; mi++) {
                uint32_t addr = aB + aOff + (uint32_t)(mi * 16 * GLDH * 2) + (uint32_t)(kk * 32);
                LDSM_X4(a[mi][0], a[mi][1], a[mi][2], a[mi][3], addr);
            }
#pragma unroll
            for (int p = 0; p < 4; p++) {
                uint32_t addr = bB + bOff + (uint32_t)(p * 16 * GLDH * 2) + (uint32_t)(kk * 32);
                uint32_t r0, r1, r2, r3;
                LDSM_X4(r0, r1, r2, r3, addr);
                bf[2 * p][0] = r0; bf[2 * p][1] = r1;
                bf[2 * p + 1][0] = r2; bf[2 * p + 1][1] = r3;
            }
#pragma unroll
            for (int mi = 0; mi < 2; mi++)
#pragma unroll
                for (int ni = 0; ni < 8; ni++)
                    MMA_F16(acc[mi][ni], a[mi][0], a[mi][1], a[mi][2], a[mi][3],
                            bf[ni][0], bf[ni][1]);
        }
        if (it + 1 < NIT) G_STS(buf ^ 1);
        __syncthreads();
    }

    const int g  = lane >> 2;
    const int cq = (lane & 3) * 2;
#pragma unroll
    for (int mi = 0; mi < 2; mi++) {
        const int row0 = rowBase + warpM + mi * 16 + g;
#pragma unroll
        for (int ni = 0; ni < 8; ni++) {
            const int col = colBase + warpN + ni * 8 + cq;
            float b0 = 0.f, b1 = 0.f;
            if (HAS_BIAS) { b0 = bias[col]; b1 = bias[col + 1]; }
            *(float2*)&C[(size_t)row0 * N + col] =
                make_float2(acc[mi][ni][0] + b0, acc[mi][ni][1] + b1);
            *(float2*)&C[(size_t)(row0 + 8) * N + col] =
                make_float2(acc[mi][ni][2] + b0, acc[mi][ni][3] + b1);
        }
    }
#undef G_LOAD
#undef G_STS
}

// =========================================================================
// CPB MLP table + bias gather (tiny, unchanged)
// =========================================================================
__global__ __launch_bounds__(512)
void cpb_tbl_kernel(const float* __restrict__ rel_table,
                    const float* __restrict__ w1,
                    const float* __restrict__ b1,
                    const float* __restrict__ w2,
                    float* __restrict__ tbl)
{
    __shared__ float hid[CPBH];
    int p = blockIdx.x;
    float t0 = rel_table[2 * p], t1 = rel_table[2 * p + 1];
    int j = threadIdx.x;
    hid[j] = fmaxf(t0 * w1[2 * j] + t1 * w1[2 * j + 1] + b1[j], 0.f);
    __syncthreads();

    int warp = j >> 5, lane = j & 31;
    const float* w2h = w2 + warp * CPBH;
    float s = 0.f;
#pragma unroll
    for (int q = lane; q < CPBH; q += 32) s += hid[q] * w2h[q];
#pragma unroll
    for (int o = 16; o > 0; o >>= 1) s += __shfl_xor_sync(0xffffffffu, s, o);
    if (lane == 0) tbl[p * HEADS + warp] = s;
}

__global__ void bias_gather_kernel(const float* __restrict__ tbl,
                                   const int* __restrict__ rel_index,
                                   float* __restrict__ bias)
{
    int t = blockIdx.x * blockDim.x + threadIdx.x;
    const int TOT = HEADS * NTOK * NTOK;
    if (t >= TOT) return;
    int h  = t / (NTOK * NTOK);
    int ij = t % (NTOK * NTOK);
    float x = tbl[rel_index[ij] * HEADS + h];
    bias[(size_t)h * NTOK * NTOK + ij] = 16.f / (1.f + __expf(-x));
}

// =========================================================================
// Window attention v6 (= R10 v4 + early bias/mask prefetch into acc):
// split-fp16 QK (3 terms), plain-fp16 PV, 18 warps / CTA.
// bias+mask LDGs issue BEFORE the barrier + MMA loop (latency hidden);
// MMAs accumulate qk on top of acc = bias + mask.
// =========================================================================
#define KSTR_H 40
#define VSTR_H 152
#define PVSTR  18

#define AK_KHI 0
#define AK_KLO (AK_KHI + NTOK * KSTR_H * 2)
#define AK_VHI (AK_KLO + NTOK * KSTR_H * 2)
#define AK_PVB (AK_VHI + DHEAD * VSTR_H * 2)
#define AK_SUM (AK_PVB + 9 * 32 * PVSTR * 4)
#define ATTN_SMEM_BYTES (AK_SUM + 9 * 2 * 32 * 4)

__global__ __launch_bounds__(576, 1)
void attn_tc6_kernel(const float* __restrict__ qkv,
                     const float* __restrict__ bias,
                     const float* __restrict__ mask,
                     const float* __restrict__ logit_scale,
                     float* __restrict__ out)
{
    extern __shared__ __align__(16) char dsm[];

    const int h = blockIdx.x;
    const int b = blockIdx.y;
    const int w = b & (NW - 1);

    const int tid  = threadIdx.x;
    const int lane = tid & 31;
    const int warp = tid >> 5;
    const int pair = warp % 9;
    const int half = warp / 9;
    const int ng   = half ? 5 : 4;
    const int hbase = half ? 64 : 0;
    const int g  = lane >> 2;
    const int t  = lane & 3;
    const int R0 = pair * 16;

    const float scale = __expf(fminf(logit_scale[h], 4.60517018598809f));
    const float* base = qkv + (size_t)b * NTOK * QKVC + h * DHEAD;

    __half* knHi = (__half*)(dsm + AK_KHI);
    __half* knLo = (__half*)(dsm + AK_KLO);
    __half* vtHi = (__half*)(dsm + AK_VHI);
    float*  pvb  = (float*)(dsm + AK_PVB);
    float*  sumb = (float*)(dsm + AK_SUM);
    const uint32_t knHiB = s2u(knHi);
    const uint32_t knLoB = s2u(knLo);
    const uint32_t vtHiB = s2u(vtHi);

    // ---------- load K (normalized, hi/lo fp16) and V^T (hi fp16) ----
#pragma unroll
    for (int i = 0; i < 8; i++) {
        int j = warp * 8 + i;
        float kv = base[(size_t)j * QKVC + CDIM + lane];
        float s = kv * kv;
#pragma unroll
        for (int o = 16; o > 0; o >>= 1) s += __shfl_xor_sync(0xffffffffu, s, o);
        kv *= rsqrtf(s);
        __half khi = __float2half_rn(kv);
        knHi[j * KSTR_H + lane] = khi;
        knLo[j * KSTR_H + lane] = __float2half_rn(kv - __half2float(khi));

        float vv = base[(size_t)j * QKVC + 2 * CDIM + lane];
        vtHi[lane * VSTR_H + j] = __float2half_rn(vv);
    }

    // ---------- Q fragments (normalized + scaled, split fp16) ----------
    uint32_t qah[2][4], qal[2][4];
    {
        const float* q0 = base + (size_t)(R0 + g) * QKVC;
        const float* q1 = base + (size_t)(R0 + g + 8) * QKVC;
        float e0[2][4], e1[2][4];
#pragma unroll
        for (int kc = 0; kc < 2; kc++) {
            e0[kc][0] = q0[16 * kc + 2 * t];     e0[kc][1] = q0[16 * kc + 2 * t + 1];
            e0[kc][2] = q0[16 * kc + 8 + 2 * t]; e0[kc][3] = q0[16 * kc + 9 + 2 * t];
            e1[kc][0] = q1[16 * kc + 2 * t];     e1[kc][1] = q1[16 * kc + 2 * t + 1];
            e1[kc][2] = q1[16 * kc + 8 + 2 * t]; e1[kc][3] = q1[16 * kc + 9 + 2 * t];
        }
        float s0 = 0.f, s1 = 0.f;
#pragma unroll
        for (int kc = 0; kc < 2; kc++)
#pragma unroll
            for (int i = 0; i < 4; i++) {
                s0 += e0[kc][i] * e0[kc][i];
                s1 += e1[kc][i] * e1[kc][i];
            }
        s0 += __shfl_xor_sync(0xffffffffu, s0, 1);
        s0 += __shfl_xor_sync(0xffffffffu, s0, 2);
        s1 += __shfl_xor_sync(0xffffffffu, s1, 1);
        s1 += __shfl_xor_sync(0xffffffffu, s1, 2);
        float r0 = rsqrtf(s0) * scale, r1 = rsqrtf(s1) * scale;
#pragma unroll
        for (int kc = 0; kc < 2; kc++) {
            split_pack(e0[kc][0] * r0, e0[kc][1] * r0, qah[kc][0], qal[kc][0]);
            split_pack(e1[kc][0] * r1, e1[kc][1] * r1, qah[kc][1], qal[kc][1]);
            split_pack(e0[kc][2] * r0, e0[kc][3] * r0, qah[kc][2], qal[kc][2]);
            split_pack(e1[kc][2] * r1, e1[kc][3] * r1, qah[kc][3], qal[kc][3]);
        }
    }

    // ---------- EARLY bias + mask prefetch: acc = bias + mask ----------
    // Issued before the barrier; latency overlaps barrier + LDSM/MMA loop.
    float acc[10][4];
    {
        const float* biasR0 = bias + (size_t)h * NTOK * NTOK + (size_t)(R0 + g) * NTOK + hbase + 2 * t;
        const float* biasR1 = biasR0 + 8 * NTOK;
        const float* maskR0 = mask + (size_t)w * NTOK * NTOK + (size_t)(R0 + g) * NTOK + hbase + 2 * t;
        const float* maskR1 = maskR0 + 8 * NTOK;
#pragma unroll
        for (int nt = 0; nt < 10; nt++) {
            if (nt < 2 * ng) {
                float2 bb0 = *(const float2*)(biasR0 + 8 * nt);
                float2 mm0 = *(const float2*)(maskR0 + 8 * nt);
                float2 bb1 = *(const float2*)(biasR1 + 8 * nt);
                float2 mm1 = *(const float2*)(maskR1 + 8 * nt);
                acc[nt][0] = bb0.x + mm0.x;
                acc[nt][1] = bb0.y + mm0.y;
                acc[nt][2] = bb1.x + mm1.x;
                acc[nt][3] = bb1.y + mm1.y;
            } else {
#pragma unroll
                for (int c = 0; c < 4; c++) acc[nt][c] = 0.f;
            }
        }
    }
    __syncthreads();

    // ---------- QK^T (split fp16, 3 terms) accumulating onto bias+mask ----
    const uint32_t ldsmRow = (uint32_t)((lane & 7) + ((lane & 16) ? 8 : 0));
    const uint32_t ldsmCol = (uint32_t)((lane >> 3) & 1) * 16;

#pragma unroll
    for (int kc = 0; kc < 2; kc++) {
#pragma unroll
        for (int gI = 0; gI < 5; gI++) {
            if (gI < ng) {
                uint32_t off = (uint32_t)(hbase + gI * 16 + ldsmRow) * (KSTR_H * 2)
                             + ldsmCol + (uint32_t)kc * 32;
                uint32_t bh0, bh1, bh2, bh3, bl0, bl1, bl2, bl3;
                LDSM_X4(bh0, bh1, bh2, bh3, knHiB + off);
                LDSM_X4(bl0, bl1, bl2, bl3, knLoB + off);
                MMA_F16(acc[2 * gI],     qah[kc][0], qah[kc][1], qah[kc][2], qah[kc][3], bh0, bh1);
                MMA_F16(acc[2 * gI],     qah[kc][0], qah[kc][1], qah[kc][2], qah[kc][3], bl0, bl1);
                MMA_F16(acc[2 * gI],     qal[kc][0], qal[kc][1], qal[kc][2], qal[kc][3], bh0, bh1);
                MMA_F16(acc[2 * gI + 1], qah[kc][0], qah[kc][1], qah[kc][2], qah[kc][3], bh2, bh3);
                MMA_F16(acc[2 * gI + 1], qah[kc][0], qah[kc][1], qah[kc][2], qah[kc][3], bl2, bl3);
                MMA_F16(acc[2 * gI + 1], qal[kc][0], qal[kc][1], qal[kc][2], qal[kc][3], bh2, bh3);
            }
        }
    }

    // ---------- local max, exp, local sums ----------
    float mx0 = -1e30f, mx1 = -1e30f, sm0 = 0.f, sm1 = 0.f;
    {
#pragma unroll
        for (int nt = 0; nt < 10; nt++) {
            if (nt < 2 * ng) {
                mx0 = fmaxf(mx0, fmaxf(acc[nt][0], acc[nt][1]));
                mx1 = fmaxf(mx1, fmaxf(acc[nt][2], acc[nt][3]));
            }
        }
        mx0 = fmaxf(mx0, __shfl_xor_sync(0xffffffffu, mx0, 1));
        mx0 = fmaxf(mx0, __shfl_xor_sync(0xffffffffu, mx0, 2));
        mx1 = fmaxf(mx1, __shfl_xor_sync(0xffffffffu, mx1, 1));
        mx1 = fmaxf(mx1, __shfl_xor_sync(0xffffffffu, mx1, 2));
#pragma unroll
        for (int nt = 0; nt < 10; nt++) {
            if (nt < 2 * ng) {
                acc[nt][0] = __expf(acc[nt][0] - mx0);
                acc[nt][1] = __expf(acc[nt][1] - mx0);
                acc[nt][2] = __expf(acc[nt][2] - mx1);
                acc[nt][3] = __expf(acc[nt][3] - mx1);
                sm0 += acc[nt][0] + acc[nt][1];
                sm1 += acc[nt][2] + acc[nt][3];
            }
        }
        sm0 += __shfl_xor_sync(0xffffffffu, sm0, 1);
        sm0 += __shfl_xor_sync(0xffffffffu, sm0, 2);
        sm1 += __shfl_xor_sync(0xffffffffu, sm1, 1);
        sm1 += __shfl_xor_sync(0xffffffffu, sm1, 2);
        if (t == 0) {
            float* sb = sumb + (pair * 2 + half) * 32;
            sb[g]          = sm0;
            sb[g + 8]      = sm1;
            sb[16 + g]     = mx0;
            sb[16 + g + 8] = mx1;
        }
    }

    // ---------- PV (plain fp16: P_hi x V_hi) ----------
    float pv[4][4];
#pragma unroll
    for (int nt = 0; nt < 4; nt++)
#pragma unroll
        for (int c = 0; c < 4; c++) pv[nt][c] = 0.f;

#pragma unroll
    for (int kc2 = 0; kc2 < 5; kc2++) {
        if (kc2 < ng) {
            uint32_t ph[4];
            ph[0] = pack_h2(acc[2 * kc2][0],     acc[2 * kc2][1]);
            ph[1] = pack_h2(acc[2 * kc2][2],     acc[2 * kc2][3]);
            ph[2] = pack_h2(acc[2 * kc2 + 1][0], acc[2 * kc2 + 1][1]);
            ph[3] = pack_h2(acc[2 * kc2 + 1][2], acc[2 * kc2 + 1][3]);
            const uint32_t gk = (uint32_t)((hbase >> 4) + kc2);
#pragma unroll
            for (int p = 0; p < 2; p++) {
                uint32_t off = (uint32_t)(p * 16 + ldsmRow) * (VSTR_H * 2)
                             + ldsmCol + gk * 32;
                uint32_t bh0, bh1, bh2, bh3;
                LDSM_X4(bh0, bh1, bh2, bh3, vtHiB + off);
                MMA_F16(pv[2 * p],     ph[0], ph[1], ph[2], ph[3], bh0, bh1);
                MMA_F16(pv[2 * p + 1], ph[0], ph[1], ph[2], ph[3], bh2, bh3);
            }
        }
    }

    // ---------- pairwise combine (max-corrected) + epilogue ----------
    if (half == 1) {
        float* pb = pvb + (pair * 32 + lane) * PVSTR;
#pragma unroll
        for (int nt = 0; nt < 4; nt++) {
            *(float2*)(pb + nt * 4)     = make_float2(pv[nt][0], pv[nt][1]);
            *(float2*)(pb + nt * 4 + 2) = make_float2(pv[nt][2], pv[nt][3]);
        }
    }
    __syncthreads();
    if (half == 0) {
        const float* sbO = sumb + (pair * 2 + 1) * 32;
        const float smO0 = sbO[g],      mxO0 = sbO[16 + g];
        const float smO1 = sbO[g + 8],  mxO1 = sbO[16 + g + 8];
        const float M0 = fmaxf(mx0, mxO0);
        const float M1 = fmaxf(mx1, mxO1);
        const float fl0 = __expf(mx0 - M0), fo0 = __expf(mxO0 - M0);
        const float fl1 = __expf(mx1 - M1), fo1 = __expf(mxO1 - M1);
        const float inv0 = 1.f / (sm0 * fl0 + smO0 * fo0);
        const float inv1 = 1.f / (sm1 * fl1 + smO1 * fo1);
        const float* pb = pvb + (pair * 32 + lane) * PVSTR;
        float* o0 = out + ((size_t)b * NTOK + R0 + g) * CDIM + h * DHEAD + 2 * t;
        float* o1 = o0 + (size_t)8 * CDIM;
#pragma unroll
        for (int nt = 0; nt < 4; nt++) {
            float2 q0 = *(const float2*)(pb + nt * 4);
            float2 q1 = *(const float2*)(pb + nt * 4 + 2);
            *(float2*)(o0 + 8 * nt) = make_float2((pv[nt][0] * fl0 + q0.x * fo0) * inv0,
                                                  (pv[nt][1] * fl0 + q0.y * fo0) * inv0);
            *(float2*)(o1 + 8 * nt) = make_float2((pv[nt][2] * fl1 + q1.x * fo1) * inv1,
                                                  (pv[nt][3] * fl1 + q1.y * fo1) * inv1);
        }
    }
}

// =========================================================================
// launch
// =========================================================================
extern "C" void kernel_launch(void* const* d_in, const int* in_sizes, int n_in,
                              void* d_out, int out_size)
{
    const float* x           = (const float*)d_in[0];
    const float* mask        = (const float*)d_in[1];
    const float* qkv_w       = (const float*)d_in[2];
    const float* logit_scale = (const float*)d_in[3];
    const float* cpb_w1      = (const float*)d_in[4];
    const float* cpb_b1      = (const float*)d_in[5];
    const float* cpb_w2      = (const float*)d_in[6];
    const float* proj_w      = (const float*)d_in[7];
    const float* proj_b      = (const float*)d_in[8];
    const float* rel_table   = (const float*)d_in[9];
    const int*   rel_index   = (const int*)d_in[10];
    float* out = (float*)d_out;

    float *qkv, *att, *tbl, *bias;
    cudaGetSymbolAddress((void**)&qkv,  g_qkv);
    cudaGetSymbolAddress((void**)&att,  g_att);
    cudaGetSymbolAddress((void**)&tbl,  g_tbl);
    cudaGetSymbolAddress((void**)&bias, g_bias);

    cudaFuncSetAttribute(gemm_f16_nt<false>,
                         cudaFuncAttributeMaxDynamicSharedMemorySize, GT_SMEM_BYTES);
    cudaFuncSetAttribute(gemm_f16_nt<true>,
                         cudaFuncAttributeMaxDynamicSharedMemorySize, GT_SMEM_BYTES);
    cudaFuncSetAttribute(attn_tc6_kernel,
                         cudaFuncAttributeMaxDynamicSharedMemorySize, ATTN_SMEM_BYTES);

    // 1) QKV projection (fp16 m16n8k16)
    {
        dim3 grid(QKVC / 256, MROWS / 128);
        gemm_f16_nt<false><<<grid, 512, GT_SMEM_BYTES>>>(x, qkv_w, nullptr, qkv,
                                                         MROWS, QKVC, CDIM);
    }

    // 2) relative position bias table + gather
    cpb_tbl_kernel<<<NPOS, CPBH>>>(rel_table, cpb_w1, cpb_b1, cpb_w2, tbl);
    {
        int tot = HEADS * NTOK * NTOK;
        bias_gather_kernel<<<(tot + 255) / 256, 256>>>(tbl, rel_index, bias);
    }

    // 3) attention v6 (R10 + early bias/mask prefetch)
    {
        dim3 grid(HEADS, BWIN);
        attn_tc6_kernel<<<grid, 576, ATTN_SMEM_BYTES>>>(qkv, bias, mask, logit_scale, att);
    }

    // 4) output projection (fp16 m16n8k16)
    {
        dim3 grid(CDIM / 256, MROWS / 128);
        gemm_f16_nt<true><<<grid, 512, GT_SMEM_BYTES>>>(att, proj_w, proj_b, out,
                                                        MROWS, CDIM, CDIM);
    }
}

// round 13
// speedup vs baseline: 1.1437x; 1.0088x over previous
#include <cuda_runtime.h>
#include <cuda_bf16.h>
#include <cuda_fp16.h>
#include <math.h>
#include <stdint.h>

// ---------------- problem constants ----------------
#define BWIN   512
#define NTOK   144
#define CDIM   512
#define HEADS  16
#define DHEAD  32
#define NW     64
#define MROWS  (BWIN * NTOK)        // 73728
#define QKVC   (3 * CDIM)           // 1536
#define NPOS   (23 * 23)
#define CPBH   512

// ---------------- scratch ----------------
__device__ float g_qkv [(size_t)MROWS * QKVC];
__device__ float g_att [(size_t)MROWS * CDIM];
__device__ float g_tbl [NPOS * HEADS];
__device__ float g_bias[(size_t)HEADS * NTOK * NTOK];

__device__ __forceinline__ uint32_t s2u(const void* p) {
    return (uint32_t)__cvta_generic_to_shared(p);
}
__device__ __forceinline__ uint2 f4_to_h4(float4 v) {
    __half2 h0 = __float22half2_rn(make_float2(v.x, v.y));
    __half2 h1 = __float22half2_rn(make_float2(v.z, v.w));
    uint2 u;
    u.x = *(uint32_t*)&h0;
    u.y = *(uint32_t*)&h1;
    return u;
}
__device__ __forceinline__ void split_pack(float x, float y, uint32_t& hi, uint32_t& lo) {
    __half hx = __float2half_rn(x), hy = __float2half_rn(y);
    __half2 h = __halves2half2(hx, hy);
    hi = *(uint32_t*)&h;
    __half2 l = __floats2half2_rn(x - __half2float(hx), y - __half2float(hy));
    lo = *(uint32_t*)&l;
}
__device__ __forceinline__ uint32_t pack_h2(float x, float y) {
    __half2 h = __floats2half2_rn(x, y);
    return *(uint32_t*)&h;
}

#define MMA_F16(d, a0,a1,a2,a3, b0,b1)                                         \
    asm volatile("mma.sync.aligned.m16n8k16.row.col.f32.f16.f16.f32 "          \
                 "{%0,%1,%2,%3},{%4,%5,%6,%7},{%8,%9},{%0,%1,%2,%3};"          \
                 : "+f"(d[0]), "+f"(d[1]), "+f"(d[2]), "+f"(d[3])              \
                 : "r"(a0), "r"(a1), "r"(a2), "r"(a3), "r"(b0), "r"(b1))

#define LDSM_X4(r0,r1,r2,r3, addr)                                             \
    asm volatile("ldmatrix.sync.aligned.m8n8.x4.shared.b16 {%0,%1,%2,%3}, [%4];" \
                 : "=r"(r0), "=r"(r1), "=r"(r2), "=r"(r3) : "r"(addr))

// =========================================================================
// FP16 tensor-core GEMM (NT) — unchanged (at half-rate HMMA floor)
// =========================================================================
#define GBK    32
#define GLDH   40
#define ABUFH  (128 * GLDH)
#define BBUFH  (256 * GLDH)
#define GT_SMEM_BYTES ((2 * ABUFH + 2 * BBUFH) * 2)   // 61440

template <bool HAS_BIAS>
__global__ __launch_bounds__(512, 1)
void gemm_f16_nt(const float* __restrict__ A,
                 const float* __restrict__ B,
                 const float* __restrict__ bias,
                 float* __restrict__ C,
                 int M, int N, int K)
{
    extern __shared__ __align__(16) __half gsm[];
    __half* As = gsm;
    __half* Bs = gsm + 2 * ABUFH;

    const int tid  = threadIdx.x;
    const int lane = tid & 31;
    const int warp = tid >> 5;
    const int warpM = (warp & 3) * 32;
    const int warpN = (warp >> 2) * 64;
    const int rowBase = blockIdx.y * 128;
    const int colBase = blockIdx.x * 256;

    const int r  = tid >> 3;
    const int kq = tid & 7;
    const float* Ag = A + (size_t)(rowBase + r) * K + kq * 4;
    const float* Bg = B + (size_t)(colBase + r) * K + kq * 4;

    float4 ra[2], rb[4];

    float acc[2][8][4];
#pragma unroll
    for (int mi = 0; mi < 2; mi++)
#pragma unroll
        for (int ni = 0; ni < 8; ni++)
#pragma unroll
            for (int c = 0; c < 4; c++) acc[mi][ni][c] = 0.f;

    const uint32_t aOff = (uint32_t)((warpM + (lane & 7) + ((lane >> 3) & 1) * 8) * (GLDH * 2))
                        + (uint32_t)(lane >> 4) * 16;
    const uint32_t bOff = (uint32_t)((warpN + (lane & 7) + ((lane & 16) ? 8 : 0)) * (GLDH * 2))
                        + (uint32_t)((lane >> 3) & 1) * 16;
    const uint32_t asBase = s2u(As);
    const uint32_t bsBase = s2u(Bs);

#define G_LOAD(it)  {                                                \
        const float* ap = Ag + (it) * GBK;                           \
        const float* bp = Bg + (it) * GBK;                           \
        ra[0] = *(const float4*)(ap);                                \
        ra[1] = *(const float4*)(ap + (size_t)64 * K);               \
        rb[0] = *(const float4*)(bp);                                \
        rb[1] = *(const float4*)(bp + (size_t)64 * K);               \
        rb[2] = *(const float4*)(bp + (size_t)128 * K);              \
        rb[3] = *(const float4*)(bp + (size_t)192 * K);              \
    }
#define G_STS(buf)  {                                                           \
        _Pragma("unroll")                                                       \
        for (int i = 0; i < 2; i++)                                             \
            *(uint2*)&As[(buf) * ABUFH + (r + 64 * i) * GLDH + kq * 4] = f4_to_h4(ra[i]); \
        _Pragma("unroll")                                                       \
        for (int i = 0; i < 4; i++)                                             \
            *(uint2*)&Bs[(buf) * BBUFH + (r + 64 * i) * GLDH + kq * 4] = f4_to_h4(rb[i]); \
    }

    G_LOAD(0); G_STS(0); __syncthreads();

    const int NIT = K / GBK;
    for (int it = 0; it < NIT; ++it) {
        const int buf = it & 1;
        if (it + 1 < NIT) G_LOAD(it + 1);

        const uint32_t aB = asBase + (uint32_t)buf * (ABUFH * 2);
        const uint32_t bB = bsBase + (uint32_t)buf * (BBUFH * 2);

#pragma unroll
        for (int kk = 0; kk < 2; kk++) {
            uint32_t a[2][4], bf[8][2];
#pragma unroll
            for (int mi = 0; mi < 2; mi++) {
                uint32_t addr = aB + aOff + (uint32_t)(mi * 16 * GLDH * 2) + (uint32_t)(kk * 32);
                LDSM_X4(a[mi][0], a[mi][1], a[mi][2], a[mi][3], addr);
            }
#pragma unroll
            for (int p = 0; p < 4; p++) {
                uint32_t addr = bB + bOff + (uint32_t)(p * 16 * GLDH * 2) + (uint32_t)(kk * 32);
                uint32_t r0, r1, r2, r3;
                LDSM_X4(r0, r1, r2, r3, addr);
                bf[2 * p][0] = r0; bf[2 * p][1] = r1;
                bf[2 * p + 1][0] = r2; bf[2 * p + 1][1] = r3;
            }
#pragma unroll
            for (int mi = 0; mi < 2; mi++)
#pragma unroll
                for (int ni = 0; ni < 8; ni++)
                    MMA_F16(acc[mi][ni], a[mi][0], a[mi][1], a[mi][2], a[mi][3],
                            bf[ni][0], bf[ni][1]);
        }
        if (it + 1 < NIT) G_STS(buf ^ 1);
        __syncthreads();
    }

    const int g  = lane >> 2;
    const int cq = (lane & 3) * 2;
#pragma unroll
    for (int mi = 0; mi < 2; mi++) {
        const int row0 = rowBase + warpM + mi * 16 + g;
#pragma unroll
        for (int ni = 0; ni < 8; ni++) {
            const int col = colBase + warpN + ni * 8 + cq;
            float b0 = 0.f, b1 = 0.f;
            if (HAS_BIAS) { b0 = bias[col]; b1 = bias[col + 1]; }
            *(float2*)&C[(size_t)row0 * N + col] =
                make_float2(acc[mi][ni][0] + b0, acc[mi][ni][1] + b1);
            *(float2*)&C[(size_t)(row0 + 8) * N + col] =
                make_float2(acc[mi][ni][2] + b0, acc[mi][ni][3] + b1);
        }
    }
#undef G_LOAD
#undef G_STS
}

// =========================================================================
// CPB MLP table + bias gather (tiny, unchanged)
// =========================================================================
__global__ __launch_bounds__(512)
void cpb_tbl_kernel(const float* __restrict__ rel_table,
                    const float* __restrict__ w1,
                    const float* __restrict__ b1,
                    const float* __restrict__ w2,
                    float* __restrict__ tbl)
{
    __shared__ float hid[CPBH];
    int p = blockIdx.x;
    float t0 = rel_table[2 * p], t1 = rel_table[2 * p + 1];
    int j = threadIdx.x;
    hid[j] = fmaxf(t0 * w1[2 * j] + t1 * w1[2 * j + 1] + b1[j], 0.f);
    __syncthreads();

    int warp = j >> 5, lane = j & 31;
    const float* w2h = w2 + warp * CPBH;
    float s = 0.f;
#pragma unroll
    for (int q = lane; q < CPBH; q += 32) s += hid[q] * w2h[q];
#pragma unroll
    for (int o = 16; o > 0; o >>= 1) s += __shfl_xor_sync(0xffffffffu, s, o);
    if (lane == 0) tbl[p * HEADS + warp] = s;
}

__global__ void bias_gather_kernel(const float* __restrict__ tbl,
                                   const int* __restrict__ rel_index,
                                   float* __restrict__ bias)
{
    int t = blockIdx.x * blockDim.x + threadIdx.x;
    const int TOT = HEADS * NTOK * NTOK;
    if (t >= TOT) return;
    int h  = t / (NTOK * NTOK);
    int ij = t % (NTOK * NTOK);
    float x = tbl[rel_index[ij] * HEADS + h];
    bias[(size_t)h * NTOK * NTOK + ij] = 16.f / (1.f + __expf(-x));
}

// =========================================================================
// Window attention v7 (= v6 + fully front-batched global loads):
// ALL per-thread LDGs (K/V rows, Q elements, bias+mask) issue before any
// consumer; reductions/splits/STS run with values already in registers.
// =========================================================================
#define KSTR_H 40
#define VSTR_H 152
#define PVSTR  18

#define AK_KHI 0
#define AK_KLO (AK_KHI + NTOK * KSTR_H * 2)
#define AK_VHI (AK_KLO + NTOK * KSTR_H * 2)
#define AK_PVB (AK_VHI + DHEAD * VSTR_H * 2)
#define AK_SUM (AK_PVB + 9 * 32 * PVSTR * 4)
#define ATTN_SMEM_BYTES (AK_SUM + 9 * 2 * 32 * 4)

__global__ __launch_bounds__(576, 1)
void attn_tc7_kernel(const float* __restrict__ qkv,
                     const float* __restrict__ bias,
                     const float* __restrict__ mask,
                     const float* __restrict__ logit_scale,
                     float* __restrict__ out)
{
    extern __shared__ __align__(16) char dsm[];

    const int h = blockIdx.x;
    const int b = blockIdx.y;
    const int w = b & (NW - 1);

    const int tid  = threadIdx.x;
    const int lane = tid & 31;
    const int warp = tid >> 5;
    const int pair = warp % 9;
    const int half = warp / 9;
    const int ng   = half ? 5 : 4;
    const int hbase = half ? 64 : 0;
    const int g  = lane >> 2;
    const int t  = lane & 3;
    const int R0 = pair * 16;

    const float scale = __expf(fminf(logit_scale[h], 4.60517018598809f));
    const float* base = qkv + (size_t)b * NTOK * QKVC + h * DHEAD;

    __half* knHi = (__half*)(dsm + AK_KHI);
    __half* knLo = (__half*)(dsm + AK_KLO);
    __half* vtHi = (__half*)(dsm + AK_VHI);
    float*  pvb  = (float*)(dsm + AK_PVB);
    float*  sumb = (float*)(dsm + AK_SUM);
    const uint32_t knHiB = s2u(knHi);
    const uint32_t knLoB = s2u(knLo);
    const uint32_t vtHiB = s2u(vtHi);

    // =================== PHASE 0: issue ALL global loads ===================
    // (a) K/V rows for this warp (16 LDG)
    float kvr[8], vvr[8];
#pragma unroll
    for (int i = 0; i < 8; i++) {
        int j = warp * 8 + i;
        kvr[i] = base[(size_t)j * QKVC + CDIM + lane];
        vvr[i] = base[(size_t)j * QKVC + 2 * CDIM + lane];
    }
    // (b) Q elements (16 LDG)
    float e0[2][4], e1[2][4];
    {
        const float* q0 = base + (size_t)(R0 + g) * QKVC;
        const float* q1 = base + (size_t)(R0 + g + 8) * QKVC;
#pragma unroll
        for (int kc = 0; kc < 2; kc++) {
            e0[kc][0] = q0[16 * kc + 2 * t];     e0[kc][1] = q0[16 * kc + 2 * t + 1];
            e0[kc][2] = q0[16 * kc + 8 + 2 * t]; e0[kc][3] = q0[16 * kc + 9 + 2 * t];
            e1[kc][0] = q1[16 * kc + 2 * t];     e1[kc][1] = q1[16 * kc + 2 * t + 1];
            e1[kc][2] = q1[16 * kc + 8 + 2 * t]; e1[kc][3] = q1[16 * kc + 9 + 2 * t];
        }
    }
    // (c) bias + mask -> acc (20 LDG.64)
    float acc[10][4];
    {
        const float* biasR0 = bias + (size_t)h * NTOK * NTOK + (size_t)(R0 + g) * NTOK + hbase + 2 * t;
        const float* biasR1 = biasR0 + 8 * NTOK;
        const float* maskR0 = mask + (size_t)w * NTOK * NTOK + (size_t)(R0 + g) * NTOK + hbase + 2 * t;
        const float* maskR1 = maskR0 + 8 * NTOK;
#pragma unroll
        for (int nt = 0; nt < 10; nt++) {
            if (nt < 2 * ng) {
                float2 bb0 = *(const float2*)(biasR0 + 8 * nt);
                float2 mm0 = *(const float2*)(maskR0 + 8 * nt);
                float2 bb1 = *(const float2*)(biasR1 + 8 * nt);
                float2 mm1 = *(const float2*)(maskR1 + 8 * nt);
                acc[nt][0] = bb0.x + mm0.x;
                acc[nt][1] = bb0.y + mm0.y;
                acc[nt][2] = bb1.x + mm1.x;
                acc[nt][3] = bb1.y + mm1.y;
            } else {
#pragma unroll
                for (int c = 0; c < 4; c++) acc[nt][c] = 0.f;
            }
        }
    }

    // =================== PHASE 1: process K/V (regs -> smem) ===============
#pragma unroll
    for (int i = 0; i < 8; i++) {
        int j = warp * 8 + i;
        float kv = kvr[i];
        float s = kv * kv;
#pragma unroll
        for (int o = 16; o > 0; o >>= 1) s += __shfl_xor_sync(0xffffffffu, s, o);
        kv *= rsqrtf(s);
        __half khi = __float2half_rn(kv);
        knHi[j * KSTR_H + lane] = khi;
        knLo[j * KSTR_H + lane] = __float2half_rn(kv - __half2float(khi));
        vtHi[lane * VSTR_H + j] = __float2half_rn(vvr[i]);
    }

    // =================== PHASE 2: process Q (normalize + split) ============
    uint32_t qah[2][4], qal[2][4];
    {
        float s0 = 0.f, s1 = 0.f;
#pragma unroll
        for (int kc = 0; kc < 2; kc++)
#pragma unroll
            for (int i = 0; i < 4; i++) {
                s0 += e0[kc][i] * e0[kc][i];
                s1 += e1[kc][i] * e1[kc][i];
            }
        s0 += __shfl_xor_sync(0xffffffffu, s0, 1);
        s0 += __shfl_xor_sync(0xffffffffu, s0, 2);
        s1 += __shfl_xor_sync(0xffffffffu, s1, 1);
        s1 += __shfl_xor_sync(0xffffffffu, s1, 2);
        float r0 = rsqrtf(s0) * scale, r1 = rsqrtf(s1) * scale;
#pragma unroll
        for (int kc = 0; kc < 2; kc++) {
            split_pack(e0[kc][0] * r0, e0[kc][1] * r0, qah[kc][0], qal[kc][0]);
            split_pack(e1[kc][0] * r1, e1[kc][1] * r1, qah[kc][1], qal[kc][1]);
            split_pack(e0[kc][2] * r0, e0[kc][3] * r0, qah[kc][2], qal[kc][2]);
            split_pack(e1[kc][2] * r1, e1[kc][3] * r1, qah[kc][3], qal[kc][3]);
        }
    }
    __syncthreads();

    // ---------- QK^T (split fp16, 3 terms) accumulating onto bias+mask ----
    const uint32_t ldsmRow = (uint32_t)((lane & 7) + ((lane & 16) ? 8 : 0));
    const uint32_t ldsmCol = (uint32_t)((lane >> 3) & 1) * 16;

#pragma unroll
    for (int kc = 0; kc < 2; kc++) {
#pragma unroll
        for (int gI = 0; gI < 5; gI++) {
            if (gI < ng) {
                uint32_t off = (uint32_t)(hbase + gI * 16 + ldsmRow) * (KSTR_H * 2)
                             + ldsmCol + (uint32_t)kc * 32;
                uint32_t bh0, bh1, bh2, bh3, bl0, bl1, bl2, bl3;
                LDSM_X4(bh0, bh1, bh2, bh3, knHiB + off);
                LDSM_X4(bl0, bl1, bl2, bl3, knLoB + off);
                MMA_F16(acc[2 * gI],     qah[kc][0], qah[kc][1], qah[kc][2], qah[kc][3], bh0, bh1);
                MMA_F16(acc[2 * gI],     qah[kc][0], qah[kc][1], qah[kc][2], qah[kc][3], bl0, bl1);
                MMA_F16(acc[2 * gI],     qal[kc][0], qal[kc][1], qal[kc][2], qal[kc][3], bh0, bh1);
                MMA_F16(acc[2 * gI + 1], qah[kc][0], qah[kc][1], qah[kc][2], qah[kc][3], bh2, bh3);
                MMA_F16(acc[2 * gI + 1], qah[kc][0], qah[kc][1], qah[kc][2], qah[kc][3], bl2, bl3);
                MMA_F16(acc[2 * gI + 1], qal[kc][0], qal[kc][1], qal[kc][2], qal[kc][3], bh2, bh3);
            }
        }
    }

    // ---------- local max, exp, local sums ----------
    float mx0 = -1e30f, mx1 = -1e30f, sm0 = 0.f, sm1 = 0.f;
    {
#pragma unroll
        for (int nt = 0; nt < 10; nt++) {
            if (nt < 2 * ng) {
                mx0 = fmaxf(mx0, fmaxf(acc[nt][0], acc[nt][1]));
                mx1 = fmaxf(mx1, fmaxf(acc[nt][2], acc[nt][3]));
            }
        }
        mx0 = fmaxf(mx0, __shfl_xor_sync(0xffffffffu, mx0, 1));
        mx0 = fmaxf(mx0, __shfl_xor_sync(0xffffffffu, mx0, 2));
        mx1 = fmaxf(mx1, __shfl_xor_sync(0xffffffffu, mx1, 1));
        mx1 = fmaxf(mx1, __shfl_xor_sync(0xffffffffu, mx1, 2));
#pragma unroll
        for (int nt = 0; nt < 10; nt++) {
            if (nt < 2 * ng) {
                acc[nt][0] = __expf(acc[nt][0] - mx0);
                acc[nt][1] = __expf(acc[nt][1] - mx0);
                acc[nt][2] = __expf(acc[nt][2] - mx1);
                acc[nt][3] = __expf(acc[nt][3] - mx1);
                sm0 += acc[nt][0] + acc[nt][1];
                sm1 += acc[nt][2] + acc[nt][3];
            }
        }
        sm0 += __shfl_xor_sync(0xffffffffu, sm0, 1);
        sm0 += __shfl_xor_sync(0xffffffffu, sm0, 2);
        sm1 += __shfl_xor_sync(0xffffffffu, sm1, 1);
        sm1 += __shfl_xor_sync(0xffffffffu, sm1, 2);
        if (t == 0) {
            float* sb = sumb + (pair * 2 + half) * 32;
            sb[g]          = sm0;
            sb[g + 8]      = sm1;
            sb[16 + g]     = mx0;
            sb[16 + g + 8] = mx1;
        }
    }

    // ---------- PV (plain fp16: P_hi x V_hi) ----------
    float pv[4][4];
#pragma unroll
    for (int nt = 0; nt < 4; nt++)
#pragma unroll
        for (int c = 0; c < 4; c++) pv[nt][c] = 0.f;

#pragma unroll
    for (int kc2 = 0; kc2 < 5; kc2++) {
        if (kc2 < ng) {
            uint32_t ph[4];
            ph[0] = pack_h2(acc[2 * kc2][0],     acc[2 * kc2][1]);
            ph[1] = pack_h2(acc[2 * kc2][2],     acc[2 * kc2][3]);
            ph[2] = pack_h2(acc[2 * kc2 + 1][0], acc[2 * kc2 + 1][1]);
            ph[3] = pack_h2(acc[2 * kc2 + 1][2], acc[2 * kc2 + 1][3]);
            const uint32_t gk = (uint32_t)((hbase >> 4) + kc2);
#pragma unroll
            for (int p = 0; p < 2; p++) {
                uint32_t off = (uint32_t)(p * 16 + ldsmRow) * (VSTR_H * 2)
                             + ldsmCol + gk * 32;
                uint32_t bh0, bh1, bh2, bh3;
                LDSM_X4(bh0, bh1, bh2, bh3, vtHiB + off);
                MMA_F16(pv[2 * p],     ph[0], ph[1], ph[2], ph[3], bh0, bh1);
                MMA_F16(pv[2 * p + 1], ph[0], ph[1], ph[2], ph[3], bh2, bh3);
            }
        }
    }

    // ---------- pairwise combine (max-corrected) + epilogue ----------
    if (half == 1) {
        float* pb = pvb + (pair * 32 + lane) * PVSTR;
#pragma unroll
        for (int nt = 0; nt < 4; nt++) {
            *(float2*)(pb + nt * 4)     = make_float2(pv[nt][0], pv[nt][1]);
            *(float2*)(pb + nt * 4 + 2) = make_float2(pv[nt][2], pv[nt][3]);
        }
    }
    __syncthreads();
    if (half == 0) {
        const float* sbO = sumb + (pair * 2 + 1) * 32;
        const float smO0 = sbO[g],      mxO0 = sbO[16 + g];
        const float smO1 = sbO[g + 8],  mxO1 = sbO[16 + g + 8];
        const float M0 = fmaxf(mx0, mxO0);
        const float M1 = fmaxf(mx1, mxO1);
        const float fl0 = __expf(mx0 - M0), fo0 = __expf(mxO0 - M0);
        const float fl1 = __expf(mx1 - M1), fo1 = __expf(mxO1 - M1);
        const float inv0 = 1.f / (sm0 * fl0 + smO0 * fo0);
        const float inv1 = 1.f / (sm1 * fl1 + smO1 * fo1);
        const float* pb = pvb + (pair * 32 + lane) * PVSTR;
        float* o0 = out + ((size_t)b * NTOK + R0 + g) * CDIM + h * DHEAD + 2 * t;
        float* o1 = o0 + (size_t)8 * CDIM;
#pragma unroll
        for (int nt = 0; nt < 4; nt++) {
            float2 q0 = *(const float2*)(pb + nt * 4);
            float2 q1 = *(const float2*)(pb + nt * 4 + 2);
            *(float2*)(o0 + 8 * nt) = make_float2((pv[nt][0] * fl0 + q0.x * fo0) * inv0,
                                                  (pv[nt][1] * fl0 + q0.y * fo0) * inv0);
            *(float2*)(o1 + 8 * nt) = make_float2((pv[nt][2] * fl1 + q1.x * fo1) * inv1,
                                                  (pv[nt][3] * fl1 + q1.y * fo1) * inv1);
        }
    }
}

// =========================================================================
// launch
// =========================================================================
extern "C" void kernel_launch(void* const* d_in, const int* in_sizes, int n_in,
                              void* d_out, int out_size)
{
    const float* x           = (const float*)d_in[0];
    const float* mask        = (const float*)d_in[1];
    const float* qkv_w       = (const float*)d_in[2];
    const float* logit_scale = (const float*)d_in[3];
    const float* cpb_w1      = (const float*)d_in[4];
    const float* cpb_b1      = (const float*)d_in[5];
    const float* cpb_w2      = (const float*)d_in[6];
    const float* proj_w      = (const float*)d_in[7];
    const float* proj_b      = (const float*)d_in[8];
    const float* rel_table   = (const float*)d_in[9];
    const int*   rel_index   = (const int*)d_in[10];
    float* out = (float*)d_out;

    float *qkv, *att, *tbl, *bias;
    cudaGetSymbolAddress((void**)&qkv,  g_qkv);
    cudaGetSymbolAddress((void**)&att,  g_att);
    cudaGetSymbolAddress((void**)&tbl,  g_tbl);
    cudaGetSymbolAddress((void**)&bias, g_bias);

    cudaFuncSetAttribute(gemm_f16_nt<false>,
                         cudaFuncAttributeMaxDynamicSharedMemorySize, GT_SMEM_BYTES);
    cudaFuncSetAttribute(gemm_f16_nt<true>,
                         cudaFuncAttributeMaxDynamicSharedMemorySize, GT_SMEM_BYTES);
    cudaFuncSetAttribute(attn_tc7_kernel,
                         cudaFuncAttributeMaxDynamicSharedMemorySize, ATTN_SMEM_BYTES);

    // 1) QKV projection (fp16 m16n8k16)
    {
        dim3 grid(QKVC / 256, MROWS / 128);
        gemm_f16_nt<false><<<grid, 512, GT_SMEM_BYTES>>>(x, qkv_w, nullptr, qkv,
                                                         MROWS, QKVC, CDIM);
    }

    // 2) relative position bias table + gather
    cpb_tbl_kernel<<<NPOS, CPBH>>>(rel_table, cpb_w1, cpb_b1, cpb_w2, tbl);
    {
        int tot = HEADS * NTOK * NTOK;
        bias_gather_kernel<<<(tot + 255) / 256, 256>>>(tbl, rel_index, bias);
    }

    // 3) attention v7 (front-batched LDGs)
    {
        dim3 grid(HEADS, BWIN);
        attn_tc7_kernel<<<grid, 576, ATTN_SMEM_BYTES>>>(qkv, bias, mask, logit_scale, att);
    }

    // 4) output projection (fp16 m16n8k16)
    {
        dim3 grid(CDIM / 256, MROWS / 128);
        gemm_f16_nt<true><<<grid, 512, GT_SMEM_BYTES>>>(att, proj_w, proj_b, out,
                                                        MROWS, CDIM, CDIM);
    }
}